// round 8
// baseline (speedup 1.0000x reference)
#include <cuda_runtime.h>
#include <cuda_bf16.h>
#include <cstdint>

#define DF   64
#define DC   256
#define HF   240
#define WF   320
#define HW   (HF*WF)
#define LC   4800
#define WW   25
#define NMAX 16384
#define BST  72        // B bf16 row stride (144B, conflict-free ldmatrix)

typedef unsigned long long u64;
typedef unsigned int u32;
typedef unsigned short u16;

__device__ float g_Wfused[DC * DF];
__device__ float g_biasf[DF];
__device__ float g_cc[2 * NMAX * DF];
__device__ u16   g_Bhi[DF * BST];
__device__ u16   g_Blo[DF * BST];

// ================= helpers =================
__device__ __forceinline__ u64 ffma2(u64 a, u64 b, u64 c) {
    u64 d; asm("fma.rn.f32x2 %0, %1, %2, %3;" : "=l"(d) : "l"(a), "l"(b), "l"(c)); return d;
}
__device__ __forceinline__ u64 dup2(float x) {
    u64 d; asm("mov.b64 %0, {%1, %1};" : "=l"(d) : "f"(x)); return d;
}
__device__ __forceinline__ u64 pk2(float a, float b) {
    u64 d; asm("mov.b64 %0, {%1, %2};" : "=l"(d) : "f"(a), "f"(b)); return d;
}
__device__ __forceinline__ float2 up2(u64 v) {
    float2 r; asm("mov.b64 {%0, %1}, %2;" : "=f"(r.x), "=f"(r.y) : "l"(v)); return r;
}
__device__ __forceinline__ u32 smem_u32(const void* p) {
    u32 a; asm("{ .reg .u64 t; cvta.to.shared.u64 t, %1; cvt.u32.u64 %0, t; }" : "=r"(a) : "l"(p));
    return a;
}
__device__ __forceinline__ void ldsm_x4(u32* r, u32 addr) {
    asm volatile("ldmatrix.sync.aligned.m8n8.x4.shared.b16 {%0,%1,%2,%3}, [%4];"
                 : "=r"(r[0]), "=r"(r[1]), "=r"(r[2]), "=r"(r[3]) : "r"(addr));
}
__device__ __forceinline__ void mma_bf16(float* d, const u32* a, const u32* b) {
    asm volatile("mma.sync.aligned.m16n8k16.row.col.f32.bf16.bf16.f32 "
                 "{%0,%1,%2,%3}, {%4,%5,%6,%7}, {%8,%9}, {%0,%1,%2,%3};"
                 : "+f"(d[0]), "+f"(d[1]), "+f"(d[2]), "+f"(d[3])
                 : "r"(a[0]), "r"(a[1]), "r"(a[2]), "r"(a[3]), "r"(b[0]), "r"(b[1]));
}
__device__ __forceinline__ u32 packbf(float hi, float lo) {
    u32 d; asm("cvt.rn.bf16x2.f32 %0, %1, %2;" : "=r"(d) : "f"(hi), "f"(lo)); return d;
}

#define CP16(dst, src) asm volatile("cp.async.cg.shared.global [%0], [%1], 16;" :: "r"(dst), "l"(src))
#define CP_COMMIT()    asm volatile("cp.async.commit_group;")
#define CP_WAIT0()     asm volatile("cp.async.wait_group 0;" ::: "memory")

// ================= weight fusion =================
__global__ void fuse_weights_kernel(const float* __restrict__ Wd,
                                    const float* __restrict__ Wm,
                                    const float* __restrict__ bd,
                                    const float* __restrict__ bm) {
    int i = blockIdx.x, j = threadIdx.x;
    float acc = 0.f;
#pragma unroll
    for (int k = 0; k < DF; k++)
        acc += Wd[i * DF + k] * Wm[(DF + k) * DF + j];
    g_Wfused[i * DF + j] = acc;
    if (i == 0) {
        float b = bm[j];
#pragma unroll
        for (int k = 0; k < DF; k++)
            b += bd[k] * Wm[(DF + k) * DF + j];
        g_biasf[j] = b;
    }
}

__global__ void prep_B_kernel(const float* __restrict__ Wm) {
    int n = blockIdx.x, k = threadIdx.x;
    float v = Wm[k * DF + n];
    __nv_bfloat16 h = __float2bfloat16(v);
    float lo = v - __bfloat162float(h);
    __nv_bfloat16 l = __float2bfloat16(lo);
    g_Bhi[n * BST + k] = *(u16*)&h;
    g_Blo[n * BST + k] = *(u16*)&l;
}

// ================= coarse projection: persistent, Wfused staged once =================
#define CO_ITEMS 64
#define CO_CVSTR 260
#define CO_SCV   65536
#define CO_SMEM  (65536 + CO_ITEMS * CO_CVSTR * 4)   // 132096

__global__ __launch_bounds__(256) void coarse_kernel(
    const float* __restrict__ c0, const float* __restrict__ c1,
    const int* __restrict__ b_ids, const int* __restrict__ ci, int N)
{
    extern __shared__ char csm[];
    const u32 csb = smem_u32(csm);
    float* sWf = (float*)csm;
    float* sCv = (float*)(csm + CO_SCV);
    __shared__ int s_off[CO_ITEMS];
    __shared__ const float* s_ptr[CO_ITEMS];

    int tid = threadIdx.x;
    int total = 2 * N;
    int nBatches = (total + CO_ITEMS - 1) / CO_ITEMS;

    // stage Wfused ONCE per block
    {
        const char* wsrc = (const char*)g_Wfused;
#pragma unroll
        for (int i = 0; i < 16; i++)
            CP16(csb + tid * 16 + i * 4096, wsrc + tid * 16 + i * 4096);
    }
    CP_COMMIT();

    const int ig = tid >> 4, cgp = tid & 15;

    for (int batch = blockIdx.x; batch < nBatches; batch += gridDim.x) {
        int base = batch * CO_ITEMS;

        if (tid < CO_ITEMS) {
            int item = base + tid;
            if (item >= total) item = total - 1;
            int s = item >= N;
            int p = item - s * N;
            s_ptr[tid] = s ? c1 : c0;
            s_off[tid] = (__ldg(b_ids + p) * LC + __ldg(ci + p)) * DC;
        }
        __syncthreads();

        for (int c = tid; c < CO_ITEMS * 64; c += 256) {
            int it = c >> 6, k16 = c & 63;
            const float* src = s_ptr[it] + s_off[it] + k16 * 4;
            CP16(csb + CO_SCV + it * (CO_CVSTR * 4) + k16 * 16, src);
        }
        CP_COMMIT();
        CP_WAIT0();
        __syncthreads();

        u64 acc[4][2];
#pragma unroll
        for (int m = 0; m < 4; m++) { acc[m][0] = 0ull; acc[m][1] = 0ull; }
        const float* cv0 = sCv + (4 * ig) * CO_CVSTR;
        const float4* wv = (const float4*)sWf + cgp;

#pragma unroll 4
        for (int k = 0; k < DC; k++) {
            float4 w = wv[k * 16];
            u64 w0 = pk2(w.x, w.y), w1 = pk2(w.z, w.w);
#pragma unroll
            for (int m = 0; m < 4; m++) {
                u64 a = dup2(cv0[m * CO_CVSTR + k]);
                acc[m][0] = ffma2(a, w0, acc[m][0]);
                acc[m][1] = ffma2(a, w1, acc[m][1]);
            }
        }
        float b0 = g_biasf[cgp * 4], b1 = g_biasf[cgp * 4 + 1];
        float b2 = g_biasf[cgp * 4 + 2], b3 = g_biasf[cgp * 4 + 3];
#pragma unroll
        for (int m = 0; m < 4; m++) {
            int item = base + 4 * ig + m;
            if (item < total) {
                float2 x0 = up2(acc[m][0]), x1 = up2(acc[m][1]);
                *(float4*)(g_cc + (size_t)item * DF + cgp * 4) =
                    make_float4(x0.x + b0, x0.y + b1, x1.x + b2, x1.y + b3);
            }
        }
        __syncthreads();   // sCv consumed before next batch overwrites
    }
}

// ================= main kernel: direct-LDG fragments, 4 blocks/SM =================
#define SMB_HI 0
#define SMB_LO 9216

__global__ __launch_bounds__(128, 4) void fine_main_kernel(
    const float* __restrict__ f0, const float* __restrict__ f1,
    const int* __restrict__ b_ids, const int* __restrict__ cy,
    const int* __restrict__ cx,
    float* __restrict__ out, int N)
{
    __shared__ __align__(16) char smem[DF * BST * 2 * 2];   // 18432
    const u32 sb = smem_u32(smem);
    const int tid = threadIdx.x;
    const int wid = tid >> 5;
    const int lane = tid & 31;
    const int total = 2 * N;
    const int nGroups = (total + 3) >> 2;

    // ---- stage B (once per block) ----
    {
        const char* srcH = (const char*)g_Bhi;
        const char* srcL = (const char*)g_Blo;
        for (int i = tid * 16; i < DF * BST * 2; i += 128 * 16) {
            CP16(sb + SMB_HI + i, srcH + i);
            CP16(sb + SMB_LO + i, srcL + i);
        }
    }
    CP_COMMIT();
    CP_WAIT0();
    __syncthreads();

    const int g = lane >> 2;            // row phase 0..7
    const int c2 = (lane & 3) * 2;      // ch pair base
    const int jc = (lane & 3) * 2;

    // window offsets for the 4 pos this lane touches (clamped, deterministic)
    int woffp[4];
#pragma unroll
    for (int pi = 0; pi < 4; pi++) {
        int p = g + 8 * pi;
        if (p >= WW) p -= 8;
        int dy = p / 5;
        woffp[pi] = dy * WF + (p - dy * 5);
    }

    const u32 bRow = (u32)((((lane >> 4) & 1) * 8 + (lane & 7)) * (BST * 2));
    const u32 bCol = (u32)(((lane >> 3) & 1) * 16);

    for (int group = blockIdx.x; group < nGroups; group += gridDim.x) {
        int item = group * 4 + wid;
        int itemc = item < total ? item : total - 1;
        int s = itemc >= N;
        int p = itemc - s * N;
        const float* fsrc = s ? f1 : f0;
        int b = __ldg(b_ids + p), y = __ldg(cy + p), x = __ldg(cx + p);
        const float* fbase = fsrc + (size_t)b * (DF * HW) + (size_t)(y - 2) * WF + (x - 2);

        // ---- gather + convert in two k-halves (32 LDG burst each) ----
        u32 ah[4][2][4], al[4][2][4];   // [kt][mt][j]
#pragma unroll
        for (int kh2 = 0; kh2 < 2; kh2++) {
            float va[32];
#pragma unroll
            for (int kt2 = 0; kt2 < 2; kt2++) {
                int kt = kh2 * 2 + kt2;
#pragma unroll
                for (int pi = 0; pi < 4; pi++) {
                    const float* bpp = fbase + woffp[pi];
#pragma unroll
                    for (int jh = 0; jh < 2; jh++)
#pragma unroll
                        for (int e = 0; e < 2; e++) {
                            int ch = kt * 16 + c2 + jh * 8 + e;
                            va[kt2 * 16 + pi * 4 + jh * 2 + e] =
                                __ldg(bpp + (size_t)ch * HW);
                        }
                }
            }
#pragma unroll
            for (int kt2 = 0; kt2 < 2; kt2++) {
                int kt = kh2 * 2 + kt2;
#pragma unroll
                for (int mt = 0; mt < 2; mt++)
#pragma unroll
                    for (int j = 0; j < 4; j++) {
                        int pi = mt * 2 + (j & 1), jh = j >> 1;
                        float v0 = va[kt2 * 16 + pi * 4 + jh * 2 + 0];
                        float v1 = va[kt2 * 16 + pi * 4 + jh * 2 + 1];
                        u32 h = packbf(v1, v0);
                        float h0 = __uint_as_float(h << 16);
                        float h1 = __uint_as_float(h & 0xffff0000u);
                        ah[kt][mt][j] = h;
                        al[kt][mt][j] = packbf(v1 - h1, v0 - h0);
                    }
            }
        }

        float* ob = out + (size_t)item * (WW * DF) + jc;
        const float* ccb = g_cc + (size_t)itemc * DF + jc;

        // ---- two N-half passes ----
#pragma unroll
        for (int nh = 0; nh < 2; nh++) {
            float acc[2][4][4];
#pragma unroll
            for (int mt = 0; mt < 2; mt++)
#pragma unroll
                for (int nt = 0; nt < 4; nt++)
#pragma unroll
                    for (int q = 0; q < 4; q++) acc[mt][nt][q] = 0.f;

#pragma unroll
            for (int kt = 0; kt < 4; kt++) {
                u32 bh[2][4], bl[2][4];
#pragma unroll
                for (int ntp = 0; ntp < 2; ntp++) {
                    u32 rowBase = (u32)((nh * 2 + ntp) * 16 * (BST * 2));
                    u32 baddr = rowBase + bRow + (u32)(kt * 32) + bCol;
                    ldsm_x4(bh[ntp], sb + SMB_HI + baddr);
                    ldsm_x4(bl[ntp], sb + SMB_LO + baddr);
                }
#pragma unroll
                for (int ntp = 0; ntp < 2; ntp++)
#pragma unroll
                    for (int sub = 0; sub < 2; sub++) {
                        int nt = ntp * 2 + sub;
                        u32 bhp[2] = {bh[ntp][sub * 2], bh[ntp][sub * 2 + 1]};
                        u32 blp[2] = {bl[ntp][sub * 2], bl[ntp][sub * 2 + 1]};
#pragma unroll
                        for (int mt = 0; mt < 2; mt++) {
                            mma_bf16(acc[mt][nt], ah[kt][mt], bhp);
                            mma_bf16(acc[mt][nt], ah[kt][mt], blp);
                            mma_bf16(acc[mt][nt], al[kt][mt], bhp);
                        }
                    }
            }

            // ---- epilogue for this N-half (cc loaded here, short-lived) ----
            if (item < total) {
#pragma unroll
                for (int nt = 0; nt < 4; nt++) {
                    int ntg = nh * 4 + nt;
                    float2 cc = *(const float2*)(ccb + ntg * 8);
#pragma unroll
                    for (int mt = 0; mt < 2; mt++) {
                        int r0 = mt * 16 + g;
                        *(float2*)(ob + r0 * DF + ntg * 8) =
                            make_float2(acc[mt][nt][0] + cc.x, acc[mt][nt][1] + cc.y);
                        if (mt == 0 || g == 0) {
                            int r1 = r0 + 8;
                            *(float2*)(ob + r1 * DF + ntg * 8) =
                                make_float2(acc[mt][nt][2] + cc.x, acc[mt][nt][3] + cc.y);
                        }
                    }
                }
            }
        }
    }
}

extern "C" void kernel_launch(void* const* d_in, const int* in_sizes, int n_in,
                              void* d_out, int out_size) {
    const float* f0    = (const float*)d_in[0];
    const float* f1    = (const float*)d_in[1];
    const float* c0    = (const float*)d_in[2];
    const float* c1    = (const float*)d_in[3];
    const float* Wd    = (const float*)d_in[4];
    const float* bd    = (const float*)d_in[5];
    const float* Wm    = (const float*)d_in[6];
    const float* bm    = (const float*)d_in[7];
    const int*   b_ids = (const int*)d_in[8];
    const int*   cy    = (const int*)d_in[9];
    const int*   cx    = (const int*)d_in[10];
    const int*   ci    = (const int*)d_in[11];
    float* out = (float*)d_out;

    int N = in_sizes[8];
    int total = 2 * N;

    fuse_weights_kernel<<<DC, DF>>>(Wd, Wm, bd, bm);
    prep_B_kernel<<<DF, DF>>>(Wm);

    static int attr_set = 0;
    if (!attr_set) {
        cudaFuncSetAttribute(coarse_kernel,
                             cudaFuncAttributeMaxDynamicSharedMemorySize, CO_SMEM);
        attr_set = 1;
    }

    int nBatches = (total + CO_ITEMS - 1) / CO_ITEMS;
    int cblocks = nBatches < 152 ? nBatches : 152;
    coarse_kernel<<<cblocks, 256, CO_SMEM>>>(c0, c1, b_ids, ci, N);

    int nGroups = (total + 3) / 4;
    int mblocks = 4 * 152;
    if (mblocks > nGroups) mblocks = nGroups;
    fine_main_kernel<<<mblocks, 128>>>(f0, f1, b_ids, cy, cx, out, N);
}